// round 12
// baseline (speedup 1.0000x reference)
#include <cuda_runtime.h>
#include <cuda_bf16.h>

// NeuralODE R12: R10 (best: 2112us, unroll 8, 128thr x 7CTA, scalar fminf
// clamps) + q-form shared reciprocal (min.f32x2 from R11 removed: that
// instruction does not exist on sm_103a).
// Math: r = 1/(2^p+1), p = 2*log2(e)*(y@W1+b1) clamped <= 31,
// tanh folded into epilogue o = c - 2*sum(r*v).

#define NB    131072
#define NSEQ  150
#define ND    2
#define NH    64
#define NPRED 150
#define NSTEPS (NPRED - 1)

typedef unsigned long long u64;

__device__ __forceinline__ u64 pk(float a, float b) {
    u64 r; asm("mov.b64 %0, {%1, %2};" : "=l"(r) : "f"(a), "f"(b)); return r;
}
__device__ __forceinline__ float2 upk(u64 v) {
    float2 r; asm("mov.b64 {%0, %1}, %2;" : "=f"(r.x), "=f"(r.y) : "l"(v)); return r;
}
__device__ __forceinline__ u64 fma2(u64 a, u64 b, u64 c) {
    u64 d; asm("fma.rn.f32x2 %0, %1, %2, %3;" : "=l"(d) : "l"(a), "l"(b), "l"(c)); return d;
}
__device__ __forceinline__ u64 add2(u64 a, u64 b) {
    u64 d; asm("add.rn.f32x2 %0, %1, %2;" : "=l"(d) : "l"(a), "l"(b)); return d;
}
__device__ __forceinline__ u64 mul2(u64 a, u64 b) {
    u64 d; asm("mul.rn.f32x2 %0, %1, %2;" : "=l"(d) : "l"(a), "l"(b)); return d;
}
__device__ __forceinline__ float ex2f(float p) {
    float t; asm("ex2.approx.f32 %0, %1;" : "=f"(t) : "f"(p)); return t;
}
__device__ __forceinline__ float rcpf(float p) {
    float t; asm("rcp.approx.f32 %0, %1;" : "=f"(t) : "f"(p)); return t;
}

// Shared layout:
//   sW[jp]  (ulonglong2): { {s*wx_j, s*wx_j1}, {s*wy_j, s*wy_j1} } per hidden pair
//   sV[jp]  (ulonglong2): { {vx_j, vx_j1},     {vy_j, vy_j1} }
//   sB4[g]  (ulonglong2): { {s*b_4g, s*b_4g+1}, {s*b_4g+2, s*b_4g+3} }
//   s = 2*log2(e).
__device__ __forceinline__ void feval(float y0, float y1,
                                      const ulonglong2* __restrict__ sW,
                                      const ulonglong2* __restrict__ sB4,
                                      const ulonglong2* __restrict__ sV,
                                      float c0, float c1,
                                      float& o0, float& o1) {
    const u64 y0p  = pk(y0, y0);
    const u64 y1p  = pk(y1, y1);
    const u64 one2 = 0x3f8000003f800000ull;   // {1.0f, 1.0f}
    u64 a0a = 0ull, a1a = 0ull;
    u64 a0b = 0ull, a1b = 0ull;
#pragma unroll 8
    for (int jp = 0; jp < NH / 2; jp += 2) {
        ulonglong2 W0 = sW[jp];
        ulonglong2 W1 = sW[jp + 1];
        ulonglong2 Bg = sB4[jp >> 1];
        u64 pA = fma2(y0p, W0.x, fma2(y1p, W0.y, Bg.x));  // {p0, p1}
        u64 pB = fma2(y0p, W1.x, fma2(y1p, W1.y, Bg.y));  // {p2, p3}
        float2 a = upk(pA), b = upk(pB);

        float t0 = ex2f(fminf(a.x, 31.0f));
        float t1 = ex2f(fminf(a.y, 31.0f));
        float t2 = ex2f(fminf(b.x, 31.0f));
        float t3 = ex2f(fminf(b.y, 31.0f));

        // q-form 4-way shared reciprocal (one MUFU rcp per 4 sigmoids).
        // p <= 31 -> u <= 2^31+1, 4-product <= ~2^124 (finite).
        u64 u01 = add2(pk(t0, t1), one2);       // {u0, u1}
        u64 u23 = add2(pk(t2, t3), one2);       // {u2, u3}
        u64 w   = mul2(u01, u23);               // {u0u2, u1u3}
        float2 wf = upk(w);
        float rc  = rcpf(wf.x * wf.y);          // 1/(u0u1u2u3)
        u64 q   = mul2(pk(rc, rc), w);          // {1/(u1u3), 1/(u0u2)}
        float2 qf = upk(q);
        u64 qs  = pk(qf.y, qf.x);               // {1/(u0u2), 1/(u1u3)}
        u64 r01 = mul2(qs, u23);                // {1/u0, 1/u1}
        u64 r23 = mul2(qs, u01);                // {1/u2, 1/u3}

        ulonglong2 V0 = sV[jp];
        ulonglong2 V1 = sV[jp + 1];
        a0a = fma2(r01, V0.x, a0a);
        a1a = fma2(r01, V0.y, a1a);
        a0b = fma2(r23, V1.x, a0b);
        a1b = fma2(r23, V1.y, a1b);
    }
    float2 s0 = upk(add2(a0a, a0b));
    float2 s1 = upk(add2(a1a, a1b));
    o0 = fmaf(-2.0f, s0.x + s0.y, c0);
    o1 = fmaf(-2.0f, s1.x + s1.y, c1);
}

__global__ void __launch_bounds__(128, 7)
neural_ode_kernel(const float* __restrict__ x,
                  const float* __restrict__ W1,
                  const float* __restrict__ b1,
                  const float* __restrict__ W2,
                  const float* __restrict__ b2,
                  float* __restrict__ out) {
    __shared__ alignas(16) float4 sWf[NH / 2];
    __shared__ alignas(16) float4 sVf[NH / 2];
    __shared__ alignas(16) float4 sBf[NH / 4];
    __shared__ float sc[2];

    const int tid = threadIdx.x;
    if (tid < NH / 2) {
        const float s = 2.8853900817779268f;  // 2*log2(e)
        int j = 2 * tid;
        sWf[tid] = make_float4(s * W1[j], s * W1[j + 1],
                               s * W1[NH + j], s * W1[NH + j + 1]);
        sVf[tid] = make_float4(W2[2 * j], W2[2 * (j + 1)],
                               W2[2 * j + 1], W2[2 * (j + 1) + 1]);
    }
    if (tid < NH / 4) {
        const float s = 2.8853900817779268f;
        int j = 4 * tid;
        sBf[tid] = make_float4(s * b1[j], s * b1[j + 1],
                               s * b1[j + 2], s * b1[j + 3]);
    }
    if (tid < 2) {
        float c = b2[tid];
        for (int j = 0; j < NH; j++) c += W2[2 * j + tid];
        sc[tid] = c;
    }
    __syncthreads();

    const ulonglong2* sW  = reinterpret_cast<const ulonglong2*>(sWf);
    const ulonglong2* sV  = reinterpret_cast<const ulonglong2*>(sVf);
    const ulonglong2* sB4 = reinterpret_cast<const ulonglong2*>(sBf);

    const float c0 = sc[0];
    const float c1 = sc[1];

    const long b = (long)blockIdx.x * blockDim.x + tid;

    const float2 yin = *(const float2*)(x + b * (long)(NSEQ * ND) + (NSEQ - 1) * ND);
    float y0 = yin.x;
    float y1 = yin.y;

    float2* ob = (float2*)(out + b * (long)(NPRED * ND));
    ob[0] = make_float2(y0, y1);

    const float dt   = (float)(150.0 / 149.0);
    const float dt3  = dt * (1.0f / 3.0f);
    const float dt8  = dt * 0.125f;
    const float thrd = 1.0f / 3.0f;

#pragma unroll 1
    for (int st = 0; st < NSTEPS; st++) {
        float k1x, k1y, k2x, k2y, k3x, k3y, k4x, k4y;

        feval(y0, y1, sW, sB4, sV, c0, c1, k1x, k1y);
        feval(fmaf(dt3, k1x, y0), fmaf(dt3, k1y, y1),
              sW, sB4, sV, c0, c1, k2x, k2y);
        feval(fmaf(dt, fmaf(-thrd, k1x, k2x), y0),
              fmaf(dt, fmaf(-thrd, k1y, k2y), y1),
              sW, sB4, sV, c0, c1, k3x, k3y);
        feval(fmaf(dt, (k1x - k2x) + k3x, y0),
              fmaf(dt, (k1y - k2y) + k3y, y1),
              sW, sB4, sV, c0, c1, k4x, k4y);

        y0 = fmaf(dt8, fmaf(3.0f, k2x + k3x, k1x + k4x), y0);
        y1 = fmaf(dt8, fmaf(3.0f, k2y + k3y, k1y + k4y), y1);

        ob[st + 1] = make_float2(y0, y1);
    }
}

extern "C" void kernel_launch(void* const* d_in, const int* in_sizes, int n_in,
                              void* d_out, int out_size) {
    const float* x  = (const float*)d_in[0];
    const float* W1 = (const float*)d_in[1];
    const float* b1 = (const float*)d_in[2];
    const float* W2 = (const float*)d_in[3];
    const float* b2 = (const float*)d_in[4];
    float* out = (float*)d_out;

    const int block = 128;
    const int grid  = NB / block;  // 1024 CTAs, 4096 warps
    neural_ode_kernel<<<grid, block>>>(x, W1, b1, W2, b2, out);
}

// round 13
// speedup vs baseline: 1.0529x; 1.0529x over previous
#include <cuda_runtime.h>
#include <cuda_bf16.h>

// NeuralODE R13: R10 base (best 2112us) with 8-WAY shared reciprocal:
// one MUFU rcp per 8 sigmoids (1.125 MUFU/tanh vs 1.25). Overflow/denormal
// safety via EXACT pre-scaling u' = (2^p + 1) * 2^-15 with clamp p <= 30:
// 8-product in [2^-120, 2^120+] -- always normal fp32. The 2^15 recovery
// factor and the tanh -2 are folded into V host-side (V *= -2^-14, exact).
// Fixup uses R10's validated scalar product tree + swapped-u trick.

#define NB    131072
#define NSEQ  150
#define ND    2
#define NH    64
#define NPRED 150
#define NSTEPS (NPRED - 1)

typedef unsigned long long u64;

__device__ __forceinline__ u64 pk(float a, float b) {
    u64 r; asm("mov.b64 %0, {%1, %2};" : "=l"(r) : "f"(a), "f"(b)); return r;
}
__device__ __forceinline__ float2 upk(u64 v) {
    float2 r; asm("mov.b64 {%0, %1}, %2;" : "=f"(r.x), "=f"(r.y) : "l"(v)); return r;
}
__device__ __forceinline__ u64 fma2(u64 a, u64 b, u64 c) {
    u64 d; asm("fma.rn.f32x2 %0, %1, %2, %3;" : "=l"(d) : "l"(a), "l"(b), "l"(c)); return d;
}
__device__ __forceinline__ u64 add2(u64 a, u64 b) {
    u64 d; asm("add.rn.f32x2 %0, %1, %2;" : "=l"(d) : "l"(a), "l"(b)); return d;
}
__device__ __forceinline__ u64 mul2(u64 a, u64 b) {
    u64 d; asm("mul.rn.f32x2 %0, %1, %2;" : "=l"(d) : "l"(a), "l"(b)); return d;
}
__device__ __forceinline__ float ex2f(float p) {
    float t; asm("ex2.approx.f32 %0, %1;" : "=f"(t) : "f"(p)); return t;
}
__device__ __forceinline__ float rcpf(float p) {
    float t; asm("rcp.approx.f32 %0, %1;" : "=f"(t) : "f"(p)); return t;
}

// Shared layout (per hidden pair jp = {2jp, 2jp+1}):
//   sW[jp]  (ulonglong2): { {s*wx_j, s*wx_j1}, {s*wy_j, s*wy_j1} }
//   sV[jp]  (ulonglong2): { {v~x_j, v~x_j1}, {v~y_j, v~y_j1} },  v~ = -2^-14 * W2
//   sB4[g]  (ulonglong2): biases for 4 units
//   s = 2*log2(e). o = c + sum over j of (2^15/u_j) * v~_j,  u = 2^p + 1, p<=30.
__device__ __forceinline__ void feval(float y0, float y1,
                                      const ulonglong2* __restrict__ sW,
                                      const ulonglong2* __restrict__ sB4,
                                      const ulonglong2* __restrict__ sV,
                                      float c0, float c1,
                                      float& o0, float& o1) {
    const u64 y0p = pk(y0, y0);
    const u64 y1p = pk(y1, y1);
    const u64 c15 = 0x3800000038000000ull;   // {2^-15, 2^-15}
    u64 a0a = 0ull, a1a = 0ull;
    u64 a0b = 0ull, a1b = 0ull;
#pragma unroll 4
    for (int jp = 0; jp < NH / 2; jp += 4) {   // 8 hidden units per iteration
        ulonglong2 Wq0 = sW[jp];
        ulonglong2 Wq1 = sW[jp + 1];
        ulonglong2 Wq2 = sW[jp + 2];
        ulonglong2 Wq3 = sW[jp + 3];
        ulonglong2 Bg0 = sB4[jp >> 1];
        ulonglong2 Bg1 = sB4[(jp >> 1) + 1];
        u64 pA = fma2(y0p, Wq0.x, fma2(y1p, Wq0.y, Bg0.x));  // {p0, p1}
        u64 pB = fma2(y0p, Wq1.x, fma2(y1p, Wq1.y, Bg0.y));  // {p2, p3}
        u64 pC = fma2(y0p, Wq2.x, fma2(y1p, Wq2.y, Bg1.x));  // {p4, p5}
        u64 pD = fma2(y0p, Wq3.x, fma2(y1p, Wq3.y, Bg1.y));  // {p6, p7}
        float2 fa = upk(pA), fb = upk(pB), fc = upk(pC), fd = upk(pD);

        float t0 = ex2f(fminf(fa.x, 30.0f));
        float t1 = ex2f(fminf(fa.y, 30.0f));
        float t2 = ex2f(fminf(fb.x, 30.0f));
        float t3 = ex2f(fminf(fb.y, 30.0f));
        float t4 = ex2f(fminf(fc.x, 30.0f));
        float t5 = ex2f(fminf(fc.y, 30.0f));
        float t6 = ex2f(fminf(fd.x, 30.0f));
        float t7 = ex2f(fminf(fd.y, 30.0f));

        // u' = (t + 1) * 2^-15  (exact scaling), built in SWAPPED lane order.
        u64 u10 = fma2(pk(t1, t0), c15, c15);   // {u'1, u'0}
        u64 u32 = fma2(pk(t3, t2), c15, c15);
        u64 u54 = fma2(pk(t5, t4), c15, c15);
        u64 u76 = fma2(pk(t7, t6), c15, c15);
        float2 ua = upk(u10), ub = upk(u32), uc = upk(u54), ud = upk(u76);

        // 8-way shared reciprocal: one MUFU rcp per 8 sigmoids.
        float m01 = ua.x * ua.y;                // u'0*u'1
        float m23 = ub.x * ub.y;
        float m45 = uc.x * uc.y;
        float m67 = ud.x * ud.y;
        float A4  = m01 * m23;
        float B4  = m45 * m67;
        float rc  = rcpf(A4 * B4);              // 1/prod8, always normal
        float iA  = rc * B4;                    // 1/A4
        float iB  = rc * A4;                    // 1/B4
        float rA  = iA * m23;                   // 1/m01
        float rB  = iA * m01;                   // 1/m23
        float rC  = iB * m67;                   // 1/m45
        float rD  = iB * m45;                   // 1/m67

        // splat(r*) * swapped-u = {1/u'_even, 1/u'_odd} in natural order
        u64 r01 = mul2(pk(rA, rA), u10);        // {2^15/u0, 2^15/u1}
        u64 r23 = mul2(pk(rB, rB), u32);
        u64 r45 = mul2(pk(rC, rC), u54);
        u64 r67 = mul2(pk(rD, rD), u76);

        ulonglong2 V0 = sV[jp];
        ulonglong2 V1 = sV[jp + 1];
        ulonglong2 V2 = sV[jp + 2];
        ulonglong2 V3 = sV[jp + 3];
        a0a = fma2(r01, V0.x, a0a);
        a1a = fma2(r01, V0.y, a1a);
        a0b = fma2(r23, V1.x, a0b);
        a1b = fma2(r23, V1.y, a1b);
        a0a = fma2(r45, V2.x, a0a);
        a1a = fma2(r45, V2.y, a1a);
        a0b = fma2(r67, V3.x, a0b);
        a1b = fma2(r67, V3.y, a1b);
    }
    float2 s0 = upk(add2(a0a, a0b));
    float2 s1 = upk(add2(a1a, a1b));
    o0 = c0 + (s0.x + s0.y);    // -2 and 2^-15 folded into V
    o1 = c1 + (s1.x + s1.y);
}

__global__ void __launch_bounds__(128, 7)
neural_ode_kernel(const float* __restrict__ x,
                  const float* __restrict__ W1,
                  const float* __restrict__ b1,
                  const float* __restrict__ W2,
                  const float* __restrict__ b2,
                  float* __restrict__ out) {
    __shared__ alignas(16) float4 sWf[NH / 2];
    __shared__ alignas(16) float4 sVf[NH / 2];
    __shared__ alignas(16) float4 sBf[NH / 4];
    __shared__ float sc[2];

    const int tid = threadIdx.x;
    if (tid < NH / 2) {
        const float s  = 2.8853900817779268f;   // 2*log2(e)
        const float vs = -0.00006103515625f;    // -2 * 2^-15 = -2^-14 (exact)
        int j = 2 * tid;
        sWf[tid] = make_float4(s * W1[j], s * W1[j + 1],
                               s * W1[NH + j], s * W1[NH + j + 1]);
        sVf[tid] = make_float4(vs * W2[2 * j], vs * W2[2 * (j + 1)],
                               vs * W2[2 * j + 1], vs * W2[2 * (j + 1) + 1]);
    }
    if (tid < NH / 4) {
        const float s = 2.8853900817779268f;
        int j = 4 * tid;
        sBf[tid] = make_float4(s * b1[j], s * b1[j + 1],
                               s * b1[j + 2], s * b1[j + 3]);
    }
    if (tid < 2) {
        float c = b2[tid];
        for (int j = 0; j < NH; j++) c += W2[2 * j + tid];
        sc[tid] = c;
    }
    __syncthreads();

    const ulonglong2* sW  = reinterpret_cast<const ulonglong2*>(sWf);
    const ulonglong2* sV  = reinterpret_cast<const ulonglong2*>(sVf);
    const ulonglong2* sB4 = reinterpret_cast<const ulonglong2*>(sBf);

    const float c0 = sc[0];
    const float c1 = sc[1];

    const long b = (long)blockIdx.x * blockDim.x + tid;

    const float2 yin = *(const float2*)(x + b * (long)(NSEQ * ND) + (NSEQ - 1) * ND);
    float y0 = yin.x;
    float y1 = yin.y;

    float2* ob = (float2*)(out + b * (long)(NPRED * ND));
    ob[0] = make_float2(y0, y1);

    const float dt   = (float)(150.0 / 149.0);
    const float dt3  = dt * (1.0f / 3.0f);
    const float dt8  = dt * 0.125f;
    const float thrd = 1.0f / 3.0f;

#pragma unroll 1
    for (int st = 0; st < NSTEPS; st++) {
        float k1x, k1y, k2x, k2y, k3x, k3y, k4x, k4y;

        feval(y0, y1, sW, sB4, sV, c0, c1, k1x, k1y);
        feval(fmaf(dt3, k1x, y0), fmaf(dt3, k1y, y1),
              sW, sB4, sV, c0, c1, k2x, k2y);
        feval(fmaf(dt, fmaf(-thrd, k1x, k2x), y0),
              fmaf(dt, fmaf(-thrd, k1y, k2y), y1),
              sW, sB4, sV, c0, c1, k3x, k3y);
        feval(fmaf(dt, (k1x - k2x) + k3x, y0),
              fmaf(dt, (k1y - k2y) + k3y, y1),
              sW, sB4, sV, c0, c1, k4x, k4y);

        y0 = fmaf(dt8, fmaf(3.0f, k2x + k3x, k1x + k4x), y0);
        y1 = fmaf(dt8, fmaf(3.0f, k2y + k3y, k1y + k4y), y1);

        ob[st + 1] = make_float2(y0, y1);
    }
}

extern "C" void kernel_launch(void* const* d_in, const int* in_sizes, int n_in,
                              void* d_out, int out_size) {
    const float* x  = (const float*)d_in[0];
    const float* W1 = (const float*)d_in[1];
    const float* b1 = (const float*)d_in[2];
    const float* W2 = (const float*)d_in[3];
    const float* b2 = (const float*)d_in[4];
    float* out = (float*)d_out;

    const int block = 128;
    const int grid  = NB / block;  // 1024 CTAs, 4096 warps
    neural_ode_kernel<<<grid, block>>>(x, W1, b1, W2, b2, out);
}

// round 14
// speedup vs baseline: 1.0701x; 1.0163x over previous
#include <cuda_runtime.h>
#include <cuda_bf16.h>

// NeuralODE R14: R13 (best 2102us, 8-way shared rcp with exact 2^-15 prescale)
// with the scalar reciprocal product tree replaced by a lane-parallel packed
// tree: 9 mul2 + 3 scalar ops instead of 13 scalar FMUL + 4 mul2.
// Lane discipline: lane X = even units, lane Y = odd units; all mul2 products
// stay lane-coherent; the single horizontal step is prod = E*O before rcp.

#define NB    131072
#define NSEQ  150
#define ND    2
#define NH    64
#define NPRED 150
#define NSTEPS (NPRED - 1)

typedef unsigned long long u64;

__device__ __forceinline__ u64 pk(float a, float b) {
    u64 r; asm("mov.b64 %0, {%1, %2};" : "=l"(r) : "f"(a), "f"(b)); return r;
}
__device__ __forceinline__ float2 upk(u64 v) {
    float2 r; asm("mov.b64 {%0, %1}, %2;" : "=f"(r.x), "=f"(r.y) : "l"(v)); return r;
}
__device__ __forceinline__ u64 fma2(u64 a, u64 b, u64 c) {
    u64 d; asm("fma.rn.f32x2 %0, %1, %2, %3;" : "=l"(d) : "l"(a), "l"(b), "l"(c)); return d;
}
__device__ __forceinline__ u64 add2(u64 a, u64 b) {
    u64 d; asm("add.rn.f32x2 %0, %1, %2;" : "=l"(d) : "l"(a), "l"(b)); return d;
}
__device__ __forceinline__ u64 mul2(u64 a, u64 b) {
    u64 d; asm("mul.rn.f32x2 %0, %1, %2;" : "=l"(d) : "l"(a), "l"(b)); return d;
}
__device__ __forceinline__ float ex2f(float p) {
    float t; asm("ex2.approx.f32 %0, %1;" : "=f"(t) : "f"(p)); return t;
}
__device__ __forceinline__ float rcpf(float p) {
    float t; asm("rcp.approx.f32 %0, %1;" : "=f"(t) : "f"(p)); return t;
}

// Shared layout (per hidden pair jp = {2jp, 2jp+1}):
//   sW[jp]  (ulonglong2): { {s*wx_j, s*wx_j1}, {s*wy_j, s*wy_j1} }
//   sV[jp]  (ulonglong2): { {v~x_j, v~x_j1}, {v~y_j, v~y_j1} },  v~ = -2^-14 * W2
//   sB4[g]  (ulonglong2): biases for 4 units
//   s = 2*log2(e). o = c + sum_j (2^15/u_j) * v~_j,  u = 2^p+1, p <= 30.
__device__ __forceinline__ void feval(float y0, float y1,
                                      const ulonglong2* __restrict__ sW,
                                      const ulonglong2* __restrict__ sB4,
                                      const ulonglong2* __restrict__ sV,
                                      float c0, float c1,
                                      float& o0, float& o1) {
    const u64 y0p = pk(y0, y0);
    const u64 y1p = pk(y1, y1);
    const u64 c15 = 0x3800000038000000ull;   // {2^-15, 2^-15}
    u64 a0a = 0ull, a1a = 0ull;
    u64 a0b = 0ull, a1b = 0ull;
#pragma unroll 4
    for (int jp = 0; jp < NH / 2; jp += 4) {   // 8 hidden units per iteration
        ulonglong2 Wq0 = sW[jp];
        ulonglong2 Wq1 = sW[jp + 1];
        ulonglong2 Wq2 = sW[jp + 2];
        ulonglong2 Wq3 = sW[jp + 3];
        ulonglong2 Bg0 = sB4[jp >> 1];
        ulonglong2 Bg1 = sB4[(jp >> 1) + 1];
        u64 pA = fma2(y0p, Wq0.x, fma2(y1p, Wq0.y, Bg0.x));  // {p0, p1}
        u64 pB = fma2(y0p, Wq1.x, fma2(y1p, Wq1.y, Bg0.y));  // {p2, p3}
        u64 pC = fma2(y0p, Wq2.x, fma2(y1p, Wq2.y, Bg1.x));  // {p4, p5}
        u64 pD = fma2(y0p, Wq3.x, fma2(y1p, Wq3.y, Bg1.y));  // {p6, p7}
        float2 fa = upk(pA), fb = upk(pB), fc = upk(pC), fd = upk(pD);

        float t0 = ex2f(fminf(fa.x, 30.0f));
        float t1 = ex2f(fminf(fa.y, 30.0f));
        float t2 = ex2f(fminf(fb.x, 30.0f));
        float t3 = ex2f(fminf(fb.y, 30.0f));
        float t4 = ex2f(fminf(fc.x, 30.0f));
        float t5 = ex2f(fminf(fc.y, 30.0f));
        float t6 = ex2f(fminf(fd.x, 30.0f));
        float t7 = ex2f(fminf(fd.y, 30.0f));

        // u' = (t + 1) * 2^-15  (exact scaling), natural lane order.
        u64 U01 = fma2(pk(t0, t1), c15, c15);   // {u0, u1}
        u64 U23 = fma2(pk(t2, t3), c15, c15);   // {u2, u3}
        u64 U45 = fma2(pk(t4, t5), c15, c15);   // {u4, u5}
        u64 U67 = fma2(pk(t6, t7), c15, c15);   // {u6, u7}

        // Packed 8-way shared reciprocal: one MUFU rcp per 8 sigmoids.
        // u' in [2^-15, 2^15] -> 8-product in [2^-120, 2^120]: always normal.
        u64 P1 = mul2(U01, U23);                // {u0u2, u1u3}
        u64 P2 = mul2(U45, U67);                // {u4u6, u5u7}
        u64 P  = mul2(P1, P2);                  // {E, O} = {u0u2u4u6, u1u3u5u7}
        float2 pf = upk(P);
        float rc  = rcpf(pf.x * pf.y);          // 1/(E*O)
        u64 Ss = pk(rc * pf.y, rc * pf.x);      // {1/E, 1/O}
        u64 T1 = mul2(Ss, P2);                  // {1/(u0u2), 1/(u1u3)}
        u64 T2 = mul2(Ss, P1);                  // {1/(u4u6), 1/(u5u7)}
        u64 r01 = mul2(T1, U23);                // {1/u0, 1/u1}
        u64 r23 = mul2(T1, U01);                // {1/u2, 1/u3}
        u64 r45 = mul2(T2, U67);                // {1/u4, 1/u5}
        u64 r67 = mul2(T2, U45);                // {1/u6, 1/u7}

        ulonglong2 V0 = sV[jp];
        ulonglong2 V1 = sV[jp + 1];
        ulonglong2 V2 = sV[jp + 2];
        ulonglong2 V3 = sV[jp + 3];
        a0a = fma2(r01, V0.x, a0a);
        a1a = fma2(r01, V0.y, a1a);
        a0b = fma2(r23, V1.x, a0b);
        a1b = fma2(r23, V1.y, a1b);
        a0a = fma2(r45, V2.x, a0a);
        a1a = fma2(r45, V2.y, a1a);
        a0b = fma2(r67, V3.x, a0b);
        a1b = fma2(r67, V3.y, a1b);
    }
    float2 s0 = upk(add2(a0a, a0b));
    float2 s1 = upk(add2(a1a, a1b));
    o0 = c0 + (s0.x + s0.y);    // -2 and 2^-15 folded into V
    o1 = c1 + (s1.x + s1.y);
}

__global__ void __launch_bounds__(128, 7)
neural_ode_kernel(const float* __restrict__ x,
                  const float* __restrict__ W1,
                  const float* __restrict__ b1,
                  const float* __restrict__ W2,
                  const float* __restrict__ b2,
                  float* __restrict__ out) {
    __shared__ alignas(16) float4 sWf[NH / 2];
    __shared__ alignas(16) float4 sVf[NH / 2];
    __shared__ alignas(16) float4 sBf[NH / 4];
    __shared__ float sc[2];

    const int tid = threadIdx.x;
    if (tid < NH / 2) {
        const float s  = 2.8853900817779268f;   // 2*log2(e)
        const float vs = -0.00006103515625f;    // -2^-14 (exact)
        int j = 2 * tid;
        sWf[tid] = make_float4(s * W1[j], s * W1[j + 1],
                               s * W1[NH + j], s * W1[NH + j + 1]);
        sVf[tid] = make_float4(vs * W2[2 * j], vs * W2[2 * (j + 1)],
                               vs * W2[2 * j + 1], vs * W2[2 * (j + 1) + 1]);
    }
    if (tid < NH / 4) {
        const float s = 2.8853900817779268f;
        int j = 4 * tid;
        sBf[tid] = make_float4(s * b1[j], s * b1[j + 1],
                               s * b1[j + 2], s * b1[j + 3]);
    }
    if (tid < 2) {
        float c = b2[tid];
        for (int j = 0; j < NH; j++) c += W2[2 * j + tid];
        sc[tid] = c;
    }
    __syncthreads();

    const ulonglong2* sW  = reinterpret_cast<const ulonglong2*>(sWf);
    const ulonglong2* sV  = reinterpret_cast<const ulonglong2*>(sVf);
    const ulonglong2* sB4 = reinterpret_cast<const ulonglong2*>(sBf);

    const float c0 = sc[0];
    const float c1 = sc[1];

    const long b = (long)blockIdx.x * blockDim.x + tid;

    const float2 yin = *(const float2*)(x + b * (long)(NSEQ * ND) + (NSEQ - 1) * ND);
    float y0 = yin.x;
    float y1 = yin.y;

    float2* ob = (float2*)(out + b * (long)(NPRED * ND));
    ob[0] = make_float2(y0, y1);

    const float dt   = (float)(150.0 / 149.0);
    const float dt3  = dt * (1.0f / 3.0f);
    const float dt8  = dt * 0.125f;
    const float thrd = 1.0f / 3.0f;

#pragma unroll 1
    for (int st = 0; st < NSTEPS; st++) {
        float k1x, k1y, k2x, k2y, k3x, k3y, k4x, k4y;

        feval(y0, y1, sW, sB4, sV, c0, c1, k1x, k1y);
        feval(fmaf(dt3, k1x, y0), fmaf(dt3, k1y, y1),
              sW, sB4, sV, c0, c1, k2x, k2y);
        feval(fmaf(dt, fmaf(-thrd, k1x, k2x), y0),
              fmaf(dt, fmaf(-thrd, k1y, k2y), y1),
              sW, sB4, sV, c0, c1, k3x, k3y);
        feval(fmaf(dt, (k1x - k2x) + k3x, y0),
              fmaf(dt, (k1y - k2y) + k3y, y1),
              sW, sB4, sV, c0, c1, k4x, k4y);

        y0 = fmaf(dt8, fmaf(3.0f, k2x + k3x, k1x + k4x), y0);
        y1 = fmaf(dt8, fmaf(3.0f, k2y + k3y, k1y + k4y), y1);

        ob[st + 1] = make_float2(y0, y1);
    }
}

extern "C" void kernel_launch(void* const* d_in, const int* in_sizes, int n_in,
                              void* d_out, int out_size) {
    const float* x  = (const float*)d_in[0];
    const float* W1 = (const float*)d_in[1];
    const float* b1 = (const float*)d_in[2];
    const float* W2 = (const float*)d_in[3];
    const float* b2 = (const float*)d_in[4];
    float* out = (float*)d_out;

    const int block = 128;
    const int grid  = NB / block;  // 1024 CTAs, 4096 warps
    neural_ode_kernel<<<grid, block>>>(x, W1, b1, W2, b2, out);
}